// round 15
// baseline (speedup 1.0000x reference)
#include <cuda_runtime.h>
#include <math.h>
#include <stdint.h>

#define BATCH 1024
#define DIN 103
#define XPAD 128
#define L1W 64
#define L2W 32
#define NE 8
#define GHW 64
#define HID 256
#define DOUT 51
#define DOPAD 64

typedef unsigned long long u64;

// ---------------- scratch ----------------
__device__ float g_xs[BATCH * XPAD];
__device__ float g_enc1[BATCH * L1W];
__device__ float g_lat[BATCH * L2W];
__device__ float g_bc[BATCH * NE];
__device__ float g_h1[BATCH * HID];
__device__ float g_h2[BATCH * HID];
__device__ float g_w3p[NE * HID * DOPAD];
__device__ float g_b3p[NE * DOPAD];
__device__ float g_part[NE * BATCH * HID];

__device__ __forceinline__ u64 ffma2(u64 a, u64 b, u64 c) {
    u64 d;
    asm("fma.rn.f32x2 %0, %1, %2, %3;" : "=l"(d) : "l"(a), "l"(b), "l"(c));
    return d;
}
__device__ __forceinline__ u64 fadd2(u64 a, u64 b) {
    u64 d;
    asm("add.rn.f32x2 %0, %1, %2;" : "=l"(d) : "l"(a), "l"(b));
    return d;
}
__device__ __forceinline__ float elu1(float v) { return (v > 0.f) ? v : expm1f(v); }

// ---------------- prep: scale+pad xs, pad ew3/eb3 ----------------
__global__ void prep_kernel(const float* __restrict__ x,
                            const float* __restrict__ ew3,
                            const float* __restrict__ eb3) {
    int i = blockIdx.x * 256 + threadIdx.x;
    const int N1 = BATCH * XPAD;
    const int N2 = NE * HID * DOPAD;
    if (i < N1) {
        int b = i >> 7, c = i & 127;
        float v = 0.f;
        if (c < DIN) {
            v = x[b * DIN + c];
            if (c >= 100) v *= 100.0f;
        }
        g_xs[i] = v;
    } else if (i < N1 + N2) {
        int j = i - N1;
        int c = j & 63;
        int er = j >> 6;
        g_w3p[j] = (c < DOUT) ? ew3[er * DOUT + c] : 0.f;
    } else if (i < N1 + N2 + NE * DOPAD) {
        int j = i - N1 - N2;
        int e = j >> 6, c = j & 63;
        g_b3p[j] = (c < DOUT) ? eb3[e * DOUT + c] : 0.f;
    }
}

// ---------------- encoder: Linear + batch BN + ReLU, one block per feature ----------------
template <int IN4, int INREAL, int SIN, int SOUT>
__global__ __launch_bounds__(256)
void enc_bn_relu_kernel(const float* __restrict__ in,
                        const float* __restrict__ w, const float* __restrict__ b,
                        const float* __restrict__ gamma, const float* __restrict__ beta,
                        float* __restrict__ out) {
    const int f = blockIdx.x;
    __shared__ __align__(16) float wf[IN4 * 4];
    __shared__ float red[18];
    const int t = threadIdx.x;
    if (t < IN4 * 4) wf[t] = (t < INREAL) ? w[f * INREAL + t] : 0.f;
    __syncthreads();

    const float bf = b[f];
    float z[4];
    float s = 0.f, s2 = 0.f;
#pragma unroll
    for (int r = 0; r < 4; r++) {
        int row = t + 256 * r;
        const float4* xr = (const float4*)(in + (size_t)row * SIN);
        const float4* wv = (const float4*)wf;
        float acc = 0.f;
#pragma unroll 8
        for (int i = 0; i < IN4; i++) {
            float4 xv = xr[i];
            float4 ww = wv[i];
            acc = fmaf(xv.x, ww.x, acc);
            acc = fmaf(xv.y, ww.y, acc);
            acc = fmaf(xv.z, ww.z, acc);
            acc = fmaf(xv.w, ww.w, acc);
        }
        acc += bf;
        z[r] = acc;
        s += acc;
        s2 = fmaf(acc, acc, s2);
    }
#pragma unroll
    for (int o = 16; o > 0; o >>= 1) {
        s  += __shfl_xor_sync(0xFFFFFFFFu, s,  o);
        s2 += __shfl_xor_sync(0xFFFFFFFFu, s2, o);
    }
    int warp = t >> 5, lane = t & 31;
    if (lane == 0) { red[warp] = s; red[8 + warp] = s2; }
    __syncthreads();
    if (t == 0) {
        float S = 0.f, S2 = 0.f;
        for (int i = 0; i < 8; i++) { S += red[i]; S2 += red[8 + i]; }
        float mean = S * (1.0f / BATCH);
        float var  = S2 * (1.0f / BATCH) - mean * mean;
        float sc = gamma[f] * rsqrtf(var + 1e-5f);
        red[16] = sc;
        red[17] = beta[f] - mean * sc;
    }
    __syncthreads();
    float sc = red[16], sh = red[17];
#pragma unroll
    for (int r = 0; r < 4; r++) {
        int row = t + 256 * r;
        out[(size_t)row * SOUT + f] = fmaxf(fmaf(z[r], sc, sh), 0.f);
    }
}

// ---------------- gen GEMM (f32x2); WITHGATE: z-planes 8..15 run the gating MLP ----------------
// part[e][b][n] = sum_k A[b][k] * W[e][k][n] + bias[e][n]
// __launch_bounds__(256, 2): cap regs at 128 so 2 blocks/SM co-reside (R14: 132 regs -> 1 block/SM,
// occ 12.5%, issue 33% -- the measured bottleneck).
template <int KSIZE, int ASTRIDE, int OUTN, int INREAL, bool WITHGATE>
__global__ __launch_bounds__(256, 2)
void gen_f32x2_kernel(const float* __restrict__ A,
                      const float* __restrict__ W,
                      const float* __restrict__ bias,
                      float* __restrict__ part,
                      const float* __restrict__ lat,
                      const float* __restrict__ gw1, const float* __restrict__ gb1,
                      const float* __restrict__ gw2, const float* __restrict__ gb2,
                      const float* __restrict__ gw3, const float* __restrict__ gb3) {
    constexpr int BM = 128, BN = 128, BK = 16;
    constexpr int KT = KSIZE / BK;
    constexpr int ASTR = 2 * BM + 4;
    __shared__ __align__(16) float As2[2][BK][ASTR];   // 8320 floats
    __shared__ __align__(16) float Ws[2][BK][BN];
    __shared__ __align__(16) float sbias[BN];

    const int tid = threadIdx.x;

    if constexpr (WITHGATE) {
        if (blockIdx.z >= NE) {
            // ---- gating block: 8 rows, proven 128-block config; smem carved from As2 ----
            float* sb   = (float*)As2;
            float* sgw1 = sb;            // 32*65 = 2080
            float* sgw2 = sb + 2080;     // 64*65 = 4160
            float* sgw3 = sb + 6240;     // 64*8  = 512
            float* sgb1 = sb + 6752;     // 64
            float* sgb2 = sb + 6816;     // 64
            float* sgb3 = sb + 6880;     // 8
            float* slat = sb + 6888;     // 8*32  = 256
            float* sa1  = sb + 7144;     // 8*64  = 512
            float* sa2  = sb + 7656;     // 8*64  = 512
            float* slg  = sb + 8168;     // 8*8   = 64   (total 8232 <= 8320)

            const int gblk = (blockIdx.z - NE) * 16 + blockIdx.y * 2 + blockIdx.x; // 0..127
            const int b0 = gblk * 8;

#pragma unroll
            for (int j = 0; j < 2; j++) {
                int f = tid + 256 * j;
                int o = f >> 3, kq = (f & 7) * 4;
                float4 v = ((const float4*)gw1)[f];
                sgw1[(kq + 0) * 65 + o] = v.x;
                sgw1[(kq + 1) * 65 + o] = v.y;
                sgw1[(kq + 2) * 65 + o] = v.z;
                sgw1[(kq + 3) * 65 + o] = v.w;
            }
#pragma unroll
            for (int j = 0; j < 4; j++) {
                int f = tid + 256 * j;
                int o = f >> 4, kq = (f & 15) * 4;
                float4 v = ((const float4*)gw2)[f];
                sgw2[(kq + 0) * 65 + o] = v.x;
                sgw2[(kq + 1) * 65 + o] = v.y;
                sgw2[(kq + 2) * 65 + o] = v.z;
                sgw2[(kq + 3) * 65 + o] = v.w;
            }
            if (tid < 128) {
                int e = tid >> 4, kq = (tid & 15) * 4;
                float4 v = ((const float4*)gw3)[tid];
                sgw3[(kq + 0) * NE + e] = v.x;
                sgw3[(kq + 1) * NE + e] = v.y;
                sgw3[(kq + 2) * NE + e] = v.z;
                sgw3[(kq + 3) * NE + e] = v.w;
            }
            if (tid < GHW) { sgb1[tid] = gb1[tid]; sgb2[tid] = gb2[tid]; }
            if (tid >= 64 && tid < 64 + NE) sgb3[tid - 64] = gb3[tid - 64];
            if (tid >= 128 && tid < 192) {
                int u = tid - 128;
                int r = u >> 3, kq = (u & 7) * 4;
                float4 v = *(const float4*)(lat + (size_t)(b0 + r) * L2W + kq);
                slat[r * 32 + kq + 0] = v.x; slat[r * 32 + kq + 1] = v.y;
                slat[r * 32 + kq + 2] = v.z; slat[r * 32 + kq + 3] = v.w;
            }
            __syncthreads();

            const int ox = tid & 63;
            const int rg = tid >> 6;
            const int r0 = rg * 2, r1 = rg * 2 + 1;

            {
                float a0 = sgb1[ox], a1 = sgb1[ox];
#pragma unroll
                for (int k = 0; k < L2W; k++) {
                    float w = sgw1[k * 65 + ox];
                    a0 = fmaf(slat[r0 * 32 + k], w, a0);
                    a1 = fmaf(slat[r1 * 32 + k], w, a1);
                }
                sa1[r0 * 64 + ox] = elu1(a0);
                sa1[r1 * 64 + ox] = elu1(a1);
            }
            __syncthreads();

            {
                float a0 = sgb2[ox], a1 = sgb2[ox];
#pragma unroll
                for (int k = 0; k < GHW; k++) {
                    float w = sgw2[k * 65 + ox];
                    a0 = fmaf(sa1[r0 * 64 + k], w, a0);
                    a1 = fmaf(sa1[r1 * 64 + k], w, a1);
                }
                sa2[r0 * 64 + ox] = elu1(a0);
                sa2[r1 * 64 + ox] = elu1(a1);
            }
            __syncthreads();

            if (tid < 64) {
                int e = tid & 7, r = tid >> 3;
                float acc = sgb3[e];
#pragma unroll
                for (int k = 0; k < GHW; k++) acc = fmaf(sa2[r * 64 + k], sgw3[k * NE + e], acc);
                slg[r * NE + e] = acc;
            }
            __syncthreads();

            if (tid < 8) {
                float m = slg[tid * NE];
#pragma unroll
                for (int e = 1; e < NE; e++) m = fmaxf(m, slg[tid * NE + e]);
                float ex[NE];
                float ssum = 0.f;
#pragma unroll
                for (int e = 0; e < NE; e++) { ex[e] = expf(slg[tid * NE + e] - m); ssum += ex[e]; }
                float inv = 1.0f / ssum;
#pragma unroll
                for (int e = 0; e < NE; e++) g_bc[(size_t)(b0 + tid) * NE + e] = ex[e] * inv;
            }
            return;
        }
    }

    // ---- GEMM block ----
    const int e  = blockIdx.z;
    const int m0 = blockIdx.y * BM;
    const int n0 = blockIdx.x * BN;
    const int tx = tid & 15;
    const int ty = tid >> 4;

    const int a_m = tid >> 1;
    const int a_k = (tid & 1) * 8;
    const int w_k = tid >> 4;
    const int w_n = (tid & 15) * 8;

    const float* Wbase = W + (size_t)e * INREAL * OUTN;
    if (tid < BN) sbias[tid] = bias[(size_t)e * OUTN + n0 + tid];

    u64 acc[8][4];
#pragma unroll
    for (int i = 0; i < 8; i++)
#pragma unroll
        for (int j = 0; j < 4; j++) acc[i][j] = 0ull;

    float4 pa0, pa1, pw0, pw1;

    {
        const float* ap = A + (size_t)(m0 + a_m) * ASTRIDE + a_k;
        pa0 = *(const float4*)(ap);
        pa1 = *(const float4*)(ap + 4);
        int gk = w_k;
        if (KSIZE != INREAL) gk = (gk < INREAL) ? gk : (INREAL - 1);
        const float* wp = Wbase + (size_t)gk * OUTN + n0 + w_n;
        pw0 = *(const float4*)(wp);
        pw1 = *(const float4*)(wp + 4);
    }
    {
        ((float2*)(&As2[0][a_k + 0][2 * a_m]))[0] = make_float2(pa0.x, pa0.x);
        ((float2*)(&As2[0][a_k + 1][2 * a_m]))[0] = make_float2(pa0.y, pa0.y);
        ((float2*)(&As2[0][a_k + 2][2 * a_m]))[0] = make_float2(pa0.z, pa0.z);
        ((float2*)(&As2[0][a_k + 3][2 * a_m]))[0] = make_float2(pa0.w, pa0.w);
        ((float2*)(&As2[0][a_k + 4][2 * a_m]))[0] = make_float2(pa1.x, pa1.x);
        ((float2*)(&As2[0][a_k + 5][2 * a_m]))[0] = make_float2(pa1.y, pa1.y);
        ((float2*)(&As2[0][a_k + 6][2 * a_m]))[0] = make_float2(pa1.z, pa1.z);
        ((float2*)(&As2[0][a_k + 7][2 * a_m]))[0] = make_float2(pa1.w, pa1.w);
        *(float4*)&Ws[0][w_k][w_n]     = pw0;
        *(float4*)&Ws[0][w_k][w_n + 4] = pw1;
    }
    __syncthreads();

    for (int kt = 0; kt < KT; kt++) {
        const int buf = kt & 1;
        if (kt + 1 < KT) {
            const int k0 = (kt + 1) * BK;
            const float* ap = A + (size_t)(m0 + a_m) * ASTRIDE + k0 + a_k;
            pa0 = *(const float4*)(ap);
            pa1 = *(const float4*)(ap + 4);
            int gk = k0 + w_k;
            if (KSIZE != INREAL) gk = (gk < INREAL) ? gk : (INREAL - 1);
            const float* wp = Wbase + (size_t)gk * OUTN + n0 + w_n;
            pw0 = *(const float4*)(wp);
            pw1 = *(const float4*)(wp + 4);
        }
#pragma unroll
        for (int k = 0; k < BK; k++) {
            const float* ar = &As2[buf][k][16 * ty];
            ulonglong2 av0 = *(const ulonglong2*)(ar + 0);
            ulonglong2 av1 = *(const ulonglong2*)(ar + 4);
            ulonglong2 av2 = *(const ulonglong2*)(ar + 8);
            ulonglong2 av3 = *(const ulonglong2*)(ar + 12);
            u64 wp_[4];
#pragma unroll
            for (int j = 0; j < 4; j++)
                wp_[j] = *(const u64*)&Ws[buf][k][2 * tx + 32 * j];
            u64 ap_[8] = {av0.x, av0.y, av1.x, av1.y, av2.x, av2.y, av3.x, av3.y};
#pragma unroll
            for (int i = 0; i < 8; i++)
#pragma unroll
                for (int j = 0; j < 4; j++)
                    acc[i][j] = ffma2(ap_[i], wp_[j], acc[i][j]);
        }
        if (kt + 1 < KT) {
            const int nb = buf ^ 1;
            ((float2*)(&As2[nb][a_k + 0][2 * a_m]))[0] = make_float2(pa0.x, pa0.x);
            ((float2*)(&As2[nb][a_k + 1][2 * a_m]))[0] = make_float2(pa0.y, pa0.y);
            ((float2*)(&As2[nb][a_k + 2][2 * a_m]))[0] = make_float2(pa0.z, pa0.z);
            ((float2*)(&As2[nb][a_k + 3][2 * a_m]))[0] = make_float2(pa0.w, pa0.w);
            ((float2*)(&As2[nb][a_k + 4][2 * a_m]))[0] = make_float2(pa1.x, pa1.x);
            ((float2*)(&As2[nb][a_k + 5][2 * a_m]))[0] = make_float2(pa1.y, pa1.y);
            ((float2*)(&As2[nb][a_k + 6][2 * a_m]))[0] = make_float2(pa1.z, pa1.z);
            ((float2*)(&As2[nb][a_k + 7][2 * a_m]))[0] = make_float2(pa1.w, pa1.w);
            *(float4*)&Ws[nb][w_k][w_n]     = pw0;
            *(float4*)&Ws[nb][w_k][w_n + 4] = pw1;
            __syncthreads();
        }
    }

#pragma unroll
    for (int i = 0; i < 8; i++) {
        const int row = m0 + ty * 8 + i;
        float* pb = part + ((size_t)e * BATCH + row) * OUTN + n0;
#pragma unroll
        for (int j = 0; j < 4; j++) {
            const int n = 2 * tx + 32 * j;
            u64 sb = *(const u64*)&sbias[n];
            *(u64*)(pb + n) = fadd2(acc[i][j], sb);
        }
    }
}

// ---------------- gen layer 3: scalar double-buffered (BM=64, TM=4, BN=64) ----------------
template <int KSIZE, int ASTRIDE, int OUTN, int INREAL, int BM, int TM>
__global__ __launch_bounds__(256)
void gen_expert_kernel(const float* __restrict__ A,
                       const float* __restrict__ W,
                       const float* __restrict__ bias,
                       float* __restrict__ part) {
    constexpr int BN = 64, BK = 32;
    constexpr int KT = KSIZE / BK;
    constexpr int F4A = BM * BK / 1024;
    __shared__ __align__(16) float As[2][BK][BM + 4];
    __shared__ __align__(16) float Ws[2][BK][BN];
    __shared__ float sbias[BN];

    const int e  = blockIdx.z;
    const int m0 = blockIdx.y * BM;
    const int n0 = blockIdx.x * BN;
    const int tid = threadIdx.x;
    const int tx = tid & 15;
    const int ty = tid >> 4;

    int a_r[F4A], a_kq[F4A];
#pragma unroll
    for (int j = 0; j < F4A; j++) {
        int idx = tid * F4A + j;
        a_r[j] = idx >> 3;
        a_kq[j] = (idx & 7) * 4;
    }
    const int wk = tid >> 3;
    const int wc = (tid & 7) * 8;

    const float* Wbase = W + (size_t)e * INREAL * OUTN;
    if (tid < BN) sbias[tid] = bias[(size_t)e * OUTN + n0 + tid];

    float acc[TM][4];
#pragma unroll
    for (int i = 0; i < TM; i++)
#pragma unroll
        for (int j = 0; j < 4; j++) acc[i][j] = 0.f;

    float4 pa[F4A];
    float4 pw0, pw1;

    {
#pragma unroll
        for (int j = 0; j < F4A; j++)
            pa[j] = *(const float4*)(A + (size_t)(m0 + a_r[j]) * ASTRIDE + a_kq[j]);
        const float* wp = Wbase + (size_t)wk * OUTN + n0;
        pw0 = *(const float4*)(wp + wc);
        pw1 = *(const float4*)(wp + wc + 4);
    }
    {
#pragma unroll
        for (int j = 0; j < F4A; j++) {
            As[0][a_kq[j] + 0][a_r[j]] = pa[j].x;
            As[0][a_kq[j] + 1][a_r[j]] = pa[j].y;
            As[0][a_kq[j] + 2][a_r[j]] = pa[j].z;
            As[0][a_kq[j] + 3][a_r[j]] = pa[j].w;
        }
        *(float4*)&Ws[0][wk][wc]     = pw0;
        *(float4*)&Ws[0][wk][wc + 4] = pw1;
    }
    __syncthreads();

    for (int kt = 0; kt < KT; kt++) {
        const int buf = kt & 1;
        if (kt + 1 < KT) {
            const int k0 = (kt + 1) * BK;
#pragma unroll
            for (int j = 0; j < F4A; j++)
                pa[j] = *(const float4*)(A + (size_t)(m0 + a_r[j]) * ASTRIDE + k0 + a_kq[j]);
            const float* wp = Wbase + (size_t)(k0 + wk) * OUTN + n0;
            pw0 = *(const float4*)(wp + wc);
            pw1 = *(const float4*)(wp + wc + 4);
        }
#pragma unroll 8
        for (int k = 0; k < BK; k++) {
            float4 w = *(const float4*)&Ws[buf][k][tx * 4];
#pragma unroll
            for (int i4 = 0; i4 < TM / 4; i4++) {
                float4 a = *(const float4*)&As[buf][k][ty * TM + i4 * 4];
                acc[i4 * 4 + 0][0] = fmaf(a.x, w.x, acc[i4 * 4 + 0][0]);
                acc[i4 * 4 + 0][1] = fmaf(a.x, w.y, acc[i4 * 4 + 0][1]);
                acc[i4 * 4 + 0][2] = fmaf(a.x, w.z, acc[i4 * 4 + 0][2]);
                acc[i4 * 4 + 0][3] = fmaf(a.x, w.w, acc[i4 * 4 + 0][3]);
                acc[i4 * 4 + 1][0] = fmaf(a.y, w.x, acc[i4 * 4 + 1][0]);
                acc[i4 * 4 + 1][1] = fmaf(a.y, w.y, acc[i4 * 4 + 1][1]);
                acc[i4 * 4 + 1][2] = fmaf(a.y, w.z, acc[i4 * 4 + 1][2]);
                acc[i4 * 4 + 1][3] = fmaf(a.y, w.w, acc[i4 * 4 + 1][3]);
                acc[i4 * 4 + 2][0] = fmaf(a.z, w.x, acc[i4 * 4 + 2][0]);
                acc[i4 * 4 + 2][1] = fmaf(a.z, w.y, acc[i4 * 4 + 2][1]);
                acc[i4 * 4 + 2][2] = fmaf(a.z, w.z, acc[i4 * 4 + 2][2]);
                acc[i4 * 4 + 2][3] = fmaf(a.z, w.w, acc[i4 * 4 + 2][3]);
                acc[i4 * 4 + 3][0] = fmaf(a.w, w.x, acc[i4 * 4 + 3][0]);
                acc[i4 * 4 + 3][1] = fmaf(a.w, w.y, acc[i4 * 4 + 3][1]);
                acc[i4 * 4 + 3][2] = fmaf(a.w, w.z, acc[i4 * 4 + 3][2]);
                acc[i4 * 4 + 3][3] = fmaf(a.w, w.w, acc[i4 * 4 + 3][3]);
            }
        }
        if (kt + 1 < KT) {
            const int nb = buf ^ 1;
#pragma unroll
            for (int j = 0; j < F4A; j++) {
                As[nb][a_kq[j] + 0][a_r[j]] = pa[j].x;
                As[nb][a_kq[j] + 1][a_r[j]] = pa[j].y;
                As[nb][a_kq[j] + 2][a_r[j]] = pa[j].z;
                As[nb][a_kq[j] + 3][a_r[j]] = pa[j].w;
            }
            *(float4*)&Ws[nb][wk][wc]     = pw0;
            *(float4*)&Ws[nb][wk][wc + 4] = pw1;
            __syncthreads();
        }
    }

#pragma unroll
    for (int i = 0; i < TM; i++) {
        const int row = m0 + ty * TM + i;
        float* pp = part + ((size_t)e * BATCH + row) * OUTN + n0 + tx * 4;
        float4 o;
        o.x = acc[i][0] + sbias[tx * 4 + 0];
        o.y = acc[i][1] + sbias[tx * 4 + 1];
        o.z = acc[i][2] + sbias[tx * 4 + 2];
        o.w = acc[i][3] + sbias[tx * 4 + 3];
        *(float4*)pp = o;
    }
}

// ---------------- combine experts with bc weights (+ optional ELU), vectorized ----------------
template <bool ACT>
__global__ void combine_vec_kernel(const float* __restrict__ part, float* __restrict__ out) {
    const int i = blockIdx.x * 256 + threadIdx.x;
    if (i >= BATCH * (HID / 4)) return;
    const int b = i >> 6;
    const float* bcp = g_bc + (size_t)b * NE;
    float4 s = make_float4(0.f, 0.f, 0.f, 0.f);
#pragma unroll
    for (int e = 0; e < NE; e++) {
        float c = bcp[e];
        float4 p = ((const float4*)part)[(size_t)e * BATCH * (HID / 4) + i];
        s.x = fmaf(c, p.x, s.x);
        s.y = fmaf(c, p.y, s.y);
        s.z = fmaf(c, p.z, s.z);
        s.w = fmaf(c, p.w, s.w);
    }
    if (ACT) {
        s.x = elu1(s.x);
        s.y = elu1(s.y);
        s.z = elu1(s.z);
        s.w = elu1(s.w);
    }
    ((float4*)out)[i] = s;
}

// final combine: padded stride 64 -> write 51
__global__ void combine_final_kernel(const float* __restrict__ part, float* __restrict__ out) {
    const int i = blockIdx.x * 256 + threadIdx.x;
    if (i >= BATCH * DOUT) return;
    const int b = i / DOUT;
    const int n = i - b * DOUT;
    const float* bcp = g_bc + (size_t)b * NE;
    float s = 0.f;
#pragma unroll
    for (int e = 0; e < NE; e++)
        s = fmaf(bcp[e], part[((size_t)e * BATCH + b) * DOPAD + n], s);
    out[i] = s;
}

// ---------------- launch ----------------
extern "C" void kernel_launch(void* const* d_in, const int* in_sizes, int n_in,
                              void* d_out, int out_size) {
    const float* x      = (const float*)d_in[0];
    const float* w1     = (const float*)d_in[1];
    const float* b1     = (const float*)d_in[2];
    const float* gamma1 = (const float*)d_in[3];
    const float* beta1  = (const float*)d_in[4];
    const float* w2     = (const float*)d_in[5];
    const float* b2     = (const float*)d_in[6];
    const float* gamma2 = (const float*)d_in[7];
    const float* beta2  = (const float*)d_in[8];
    const float* gw1    = (const float*)d_in[9];
    const float* gb1    = (const float*)d_in[10];
    const float* gw2    = (const float*)d_in[11];
    const float* gb2    = (const float*)d_in[12];
    const float* gw3    = (const float*)d_in[13];
    const float* gb3    = (const float*)d_in[14];
    const float* ew1    = (const float*)d_in[15];
    const float* eb1    = (const float*)d_in[16];
    const float* ew2    = (const float*)d_in[17];
    const float* eb2    = (const float*)d_in[18];
    const float* ew3    = (const float*)d_in[19];
    const float* eb3    = (const float*)d_in[20];

    float *p_xs, *p_enc1, *p_lat, *p_h1, *p_h2, *p_part, *p_w3p, *p_b3p;
    cudaGetSymbolAddress((void**)&p_xs,   g_xs);
    cudaGetSymbolAddress((void**)&p_enc1, g_enc1);
    cudaGetSymbolAddress((void**)&p_lat,  g_lat);
    cudaGetSymbolAddress((void**)&p_h1,   g_h1);
    cudaGetSymbolAddress((void**)&p_h2,   g_h2);
    cudaGetSymbolAddress((void**)&p_part, g_part);
    cudaGetSymbolAddress((void**)&p_w3p,  g_w3p);
    cudaGetSymbolAddress((void**)&p_b3p,  g_b3p);

    const int prepN = BATCH * XPAD + NE * HID * DOPAD + NE * DOPAD;
    prep_kernel<<<(prepN + 255) / 256, 256>>>(x, ew3, eb3);

    enc_bn_relu_kernel<32, DIN, XPAD, L1W><<<L1W, 256>>>(p_xs, w1, b1, gamma1, beta1, p_enc1);
    enc_bn_relu_kernel<16, L1W, L1W, L2W><<<L2W, 256>>>(p_enc1, w2, b2, gamma2, beta2, p_lat);

    // layer 1 + gating fused: z 0..7 = expert GEMMs, z 8..15 = 128 gating blocks
    gen_f32x2_kernel<XPAD, XPAD, HID, DIN, true>
        <<<dim3(HID / 128, BATCH / 128, 2 * NE), 256>>>(
            p_xs, ew1, eb1, p_part,
            p_lat, gw1, gb1, gw2, gb2, gw3, gb3);
    combine_vec_kernel<true><<<(BATCH * HID / 4 + 255) / 256, 256>>>(p_part, p_h1);

    // layer 2: h1[1024,256] x ew2[8,256,256]
    gen_f32x2_kernel<HID, HID, HID, HID, false>
        <<<dim3(HID / 128, BATCH / 128, NE), 256>>>(
            p_h1, ew2, eb2, p_part,
            nullptr, nullptr, nullptr, nullptr, nullptr, nullptr, nullptr);
    combine_vec_kernel<true><<<(BATCH * HID / 4 + 255) / 256, 256>>>(p_part, p_h2);

    // layer 3: h2[1024,256] x w3p[8,256,64(pad)]
    gen_expert_kernel<HID, HID, DOPAD, HID, 64, 4>
        <<<dim3(1, BATCH / 64, NE), 256>>>(p_h2, p_w3p, p_b3p, p_part);
    combine_final_kernel<<<(BATCH * DOUT + 255) / 256, 256>>>(p_part, (float*)d_out);
}

// round 16
// speedup vs baseline: 1.0443x; 1.0443x over previous
#include <cuda_runtime.h>
#include <math.h>
#include <stdint.h>

#define BATCH 1024
#define DIN 103
#define XPAD 128
#define L1W 64
#define L2W 32
#define NE 8
#define GHW 64
#define HID 256
#define DOUT 51
#define DOPAD 64

typedef unsigned long long u64;

// ---------------- scratch ----------------
__device__ float g_xs[BATCH * XPAD];
__device__ float g_enc1[BATCH * L1W];
__device__ float g_lat[BATCH * L2W];
__device__ float g_bc[BATCH * NE];
__device__ float g_h1[BATCH * HID];
__device__ float g_h2[BATCH * HID];
__device__ float g_w3p[NE * HID * DOPAD];
__device__ float g_b3p[NE * DOPAD];
__device__ float g_part[NE * BATCH * HID];

__device__ __forceinline__ u64 ffma2(u64 a, u64 b, u64 c) {
    u64 d;
    asm("fma.rn.f32x2 %0, %1, %2, %3;" : "=l"(d) : "l"(a), "l"(b), "l"(c));
    return d;
}
__device__ __forceinline__ u64 fadd2(u64 a, u64 b) {
    u64 d;
    asm("add.rn.f32x2 %0, %1, %2;" : "=l"(d) : "l"(a), "l"(b));
    return d;
}
__device__ __forceinline__ float elu1(float v) { return (v > 0.f) ? v : expm1f(v); }

// ---------------- enc1 + prep fused ----------------
// Blocks 0..63: encoder layer 1 on RAW x (weights pre-scaled by the x[:,100:103]*=100 factor).
// Blocks 64..191: prep work (pad/scale xs for gen1, pad ew3/eb3 for gen3).
__global__ __launch_bounds__(256)
void enc1_prep_kernel(const float* __restrict__ x,
                      const float* __restrict__ w, const float* __restrict__ b,
                      const float* __restrict__ gamma, const float* __restrict__ beta,
                      float* __restrict__ out,
                      const float* __restrict__ ew3,
                      const float* __restrict__ eb3) {
    const int t = threadIdx.x;

    if (blockIdx.x >= L1W) {
        // ---- prep blocks ----
        const int pb = blockIdx.x - L1W;          // 0..127
        const int N1 = BATCH * XPAD;
        const int N2 = NE * HID * DOPAD;
        const int N3 = NE * DOPAD;
        const int total = N1 + N2 + N3;
        for (int i = pb * 256 + t; i < total; i += 128 * 256) {
            if (i < N1) {
                int bb = i >> 7, c = i & 127;
                float v = 0.f;
                if (c < DIN) {
                    v = x[bb * DIN + c];
                    if (c >= 100) v *= 100.0f;
                }
                g_xs[i] = v;
            } else if (i < N1 + N2) {
                int j = i - N1;
                int c = j & 63;
                int er = j >> 6;
                g_w3p[j] = (c < DOUT) ? ew3[er * DOUT + c] : 0.f;
            } else {
                int j = i - N1 - N2;
                int e = j >> 6, c = j & 63;
                g_b3p[j] = (c < DOUT) ? eb3[e * DOUT + c] : 0.f;
            }
        }
        return;
    }

    // ---- encoder layer 1 block (feature f) ----
    const int f = blockIdx.x;
    __shared__ float wf[DIN + 1];
    __shared__ float red[18];
    if (t < DIN) {
        float wv = w[f * DIN + t];
        if (t >= 100) wv *= 100.0f;        // fold xs scaling into the weight
        wf[t] = wv;
    }
    __syncthreads();

    const float bf = b[f];
    float z[4];
    float s = 0.f, s2 = 0.f;
#pragma unroll
    for (int r = 0; r < 4; r++) {
        int row = t + 256 * r;
        const float* xr = x + (size_t)row * DIN;
        float acc = 0.f;
#pragma unroll 8
        for (int i = 0; i < DIN; i++) acc = fmaf(xr[i], wf[i], acc);
        acc += bf;
        z[r] = acc;
        s += acc;
        s2 = fmaf(acc, acc, s2);
    }
#pragma unroll
    for (int o = 16; o > 0; o >>= 1) {
        s  += __shfl_xor_sync(0xFFFFFFFFu, s,  o);
        s2 += __shfl_xor_sync(0xFFFFFFFFu, s2, o);
    }
    int warp = t >> 5, lane = t & 31;
    if (lane == 0) { red[warp] = s; red[8 + warp] = s2; }
    __syncthreads();
    if (t == 0) {
        float S = 0.f, S2 = 0.f;
        for (int i = 0; i < 8; i++) { S += red[i]; S2 += red[8 + i]; }
        float mean = S * (1.0f / BATCH);
        float var  = S2 * (1.0f / BATCH) - mean * mean;
        float sc = gamma[f] * rsqrtf(var + 1e-5f);
        red[16] = sc;
        red[17] = beta[f] - mean * sc;
    }
    __syncthreads();
    float sc = red[16], sh = red[17];
#pragma unroll
    for (int r = 0; r < 4; r++) {
        int row = t + 256 * r;
        out[(size_t)row * L1W + f] = fmaxf(fmaf(z[r], sc, sh), 0.f);
    }
}

// ---------------- encoder layer 2: Linear + batch BN + ReLU (vectorized) ----------------
template <int IN4, int INREAL, int SIN, int SOUT>
__global__ __launch_bounds__(256)
void enc_bn_relu_kernel(const float* __restrict__ in,
                        const float* __restrict__ w, const float* __restrict__ b,
                        const float* __restrict__ gamma, const float* __restrict__ beta,
                        float* __restrict__ out) {
    const int f = blockIdx.x;
    __shared__ __align__(16) float wf[IN4 * 4];
    __shared__ float red[18];
    const int t = threadIdx.x;
    if (t < IN4 * 4) wf[t] = (t < INREAL) ? w[f * INREAL + t] : 0.f;
    __syncthreads();

    const float bf = b[f];
    float z[4];
    float s = 0.f, s2 = 0.f;
#pragma unroll
    for (int r = 0; r < 4; r++) {
        int row = t + 256 * r;
        const float4* xr = (const float4*)(in + (size_t)row * SIN);
        const float4* wv = (const float4*)wf;
        float acc = 0.f;
#pragma unroll 8
        for (int i = 0; i < IN4; i++) {
            float4 xv = xr[i];
            float4 ww = wv[i];
            acc = fmaf(xv.x, ww.x, acc);
            acc = fmaf(xv.y, ww.y, acc);
            acc = fmaf(xv.z, ww.z, acc);
            acc = fmaf(xv.w, ww.w, acc);
        }
        acc += bf;
        z[r] = acc;
        s += acc;
        s2 = fmaf(acc, acc, s2);
    }
#pragma unroll
    for (int o = 16; o > 0; o >>= 1) {
        s  += __shfl_xor_sync(0xFFFFFFFFu, s,  o);
        s2 += __shfl_xor_sync(0xFFFFFFFFu, s2, o);
    }
    int warp = t >> 5, lane = t & 31;
    if (lane == 0) { red[warp] = s; red[8 + warp] = s2; }
    __syncthreads();
    if (t == 0) {
        float S = 0.f, S2 = 0.f;
        for (int i = 0; i < 8; i++) { S += red[i]; S2 += red[8 + i]; }
        float mean = S * (1.0f / BATCH);
        float var  = S2 * (1.0f / BATCH) - mean * mean;
        float sc = gamma[f] * rsqrtf(var + 1e-5f);
        red[16] = sc;
        red[17] = beta[f] - mean * sc;
    }
    __syncthreads();
    float sc = red[16], sh = red[17];
#pragma unroll
    for (int r = 0; r < 4; r++) {
        int row = t + 256 * r;
        out[(size_t)row * SOUT + f] = fmaxf(fmaf(z[r], sc, sh), 0.f);
    }
}

// ---------------- gen GEMM (f32x2); WITHGATE: z-planes 8..15 run the gating MLP ----------------
// part[e][b][n] = sum_k A[b][k] * W[e][k][n] + bias[e][n]
// NOTE: natural register allocation (132 regs, 1 block/SM) measured FASTER than a
// 128-reg cap (spills); do not add a min-blocks bound here.
template <int KSIZE, int ASTRIDE, int OUTN, int INREAL, bool WITHGATE>
__global__ __launch_bounds__(256)
void gen_f32x2_kernel(const float* __restrict__ A,
                      const float* __restrict__ W,
                      const float* __restrict__ bias,
                      float* __restrict__ part,
                      const float* __restrict__ lat,
                      const float* __restrict__ gw1, const float* __restrict__ gb1,
                      const float* __restrict__ gw2, const float* __restrict__ gb2,
                      const float* __restrict__ gw3, const float* __restrict__ gb3) {
    constexpr int BM = 128, BN = 128, BK = 16;
    constexpr int KT = KSIZE / BK;
    constexpr int ASTR = 2 * BM + 4;
    __shared__ __align__(16) float As2[2][BK][ASTR];   // 8320 floats
    __shared__ __align__(16) float Ws[2][BK][BN];
    __shared__ __align__(16) float sbias[BN];

    const int tid = threadIdx.x;

    if constexpr (WITHGATE) {
        if (blockIdx.z >= NE) {
            // ---- gating block: 8 rows, proven 128-block config; smem carved from As2 ----
            float* sb   = (float*)As2;
            float* sgw1 = sb;            // 32*65 = 2080
            float* sgw2 = sb + 2080;     // 64*65 = 4160
            float* sgw3 = sb + 6240;     // 64*8  = 512
            float* sgb1 = sb + 6752;     // 64
            float* sgb2 = sb + 6816;     // 64
            float* sgb3 = sb + 6880;     // 8
            float* slat = sb + 6888;     // 8*32  = 256
            float* sa1  = sb + 7144;     // 8*64  = 512
            float* sa2  = sb + 7656;     // 8*64  = 512
            float* slg  = sb + 8168;     // 8*8   = 64   (total 8232 <= 8320)

            const int gblk = (blockIdx.z - NE) * 16 + blockIdx.y * 2 + blockIdx.x; // 0..127
            const int b0 = gblk * 8;

#pragma unroll
            for (int j = 0; j < 2; j++) {
                int f = tid + 256 * j;
                int o = f >> 3, kq = (f & 7) * 4;
                float4 v = ((const float4*)gw1)[f];
                sgw1[(kq + 0) * 65 + o] = v.x;
                sgw1[(kq + 1) * 65 + o] = v.y;
                sgw1[(kq + 2) * 65 + o] = v.z;
                sgw1[(kq + 3) * 65 + o] = v.w;
            }
#pragma unroll
            for (int j = 0; j < 4; j++) {
                int f = tid + 256 * j;
                int o = f >> 4, kq = (f & 15) * 4;
                float4 v = ((const float4*)gw2)[f];
                sgw2[(kq + 0) * 65 + o] = v.x;
                sgw2[(kq + 1) * 65 + o] = v.y;
                sgw2[(kq + 2) * 65 + o] = v.z;
                sgw2[(kq + 3) * 65 + o] = v.w;
            }
            if (tid < 128) {
                int e = tid >> 4, kq = (tid & 15) * 4;
                float4 v = ((const float4*)gw3)[tid];
                sgw3[(kq + 0) * NE + e] = v.x;
                sgw3[(kq + 1) * NE + e] = v.y;
                sgw3[(kq + 2) * NE + e] = v.z;
                sgw3[(kq + 3) * NE + e] = v.w;
            }
            if (tid < GHW) { sgb1[tid] = gb1[tid]; sgb2[tid] = gb2[tid]; }
            if (tid >= 64 && tid < 64 + NE) sgb3[tid - 64] = gb3[tid - 64];
            if (tid >= 128 && tid < 192) {
                int u = tid - 128;
                int r = u >> 3, kq = (u & 7) * 4;
                float4 v = *(const float4*)(lat + (size_t)(b0 + r) * L2W + kq);
                slat[r * 32 + kq + 0] = v.x; slat[r * 32 + kq + 1] = v.y;
                slat[r * 32 + kq + 2] = v.z; slat[r * 32 + kq + 3] = v.w;
            }
            __syncthreads();

            const int ox = tid & 63;
            const int rg = tid >> 6;
            const int r0 = rg * 2, r1 = rg * 2 + 1;

            {
                float a0 = sgb1[ox], a1 = sgb1[ox];
#pragma unroll
                for (int k = 0; k < L2W; k++) {
                    float w = sgw1[k * 65 + ox];
                    a0 = fmaf(slat[r0 * 32 + k], w, a0);
                    a1 = fmaf(slat[r1 * 32 + k], w, a1);
                }
                sa1[r0 * 64 + ox] = elu1(a0);
                sa1[r1 * 64 + ox] = elu1(a1);
            }
            __syncthreads();

            {
                float a0 = sgb2[ox], a1 = sgb2[ox];
#pragma unroll
                for (int k = 0; k < GHW; k++) {
                    float w = sgw2[k * 65 + ox];
                    a0 = fmaf(sa1[r0 * 64 + k], w, a0);
                    a1 = fmaf(sa1[r1 * 64 + k], w, a1);
                }
                sa2[r0 * 64 + ox] = elu1(a0);
                sa2[r1 * 64 + ox] = elu1(a1);
            }
            __syncthreads();

            if (tid < 64) {
                int e = tid & 7, r = tid >> 3;
                float acc = sgb3[e];
#pragma unroll
                for (int k = 0; k < GHW; k++) acc = fmaf(sa2[r * 64 + k], sgw3[k * NE + e], acc);
                slg[r * NE + e] = acc;
            }
            __syncthreads();

            if (tid < 8) {
                float m = slg[tid * NE];
#pragma unroll
                for (int e = 1; e < NE; e++) m = fmaxf(m, slg[tid * NE + e]);
                float ex[NE];
                float ssum = 0.f;
#pragma unroll
                for (int e = 0; e < NE; e++) { ex[e] = expf(slg[tid * NE + e] - m); ssum += ex[e]; }
                float inv = 1.0f / ssum;
#pragma unroll
                for (int e = 0; e < NE; e++) g_bc[(size_t)(b0 + tid) * NE + e] = ex[e] * inv;
            }
            return;
        }
    }

    // ---- GEMM block ----
    const int e  = blockIdx.z;
    const int m0 = blockIdx.y * BM;
    const int n0 = blockIdx.x * BN;
    const int tx = tid & 15;
    const int ty = tid >> 4;

    const int a_m = tid >> 1;
    const int a_k = (tid & 1) * 8;
    const int w_k = tid >> 4;
    const int w_n = (tid & 15) * 8;

    const float* Wbase = W + (size_t)e * INREAL * OUTN;
    if (tid < BN) sbias[tid] = bias[(size_t)e * OUTN + n0 + tid];

    u64 acc[8][4];
#pragma unroll
    for (int i = 0; i < 8; i++)
#pragma unroll
        for (int j = 0; j < 4; j++) acc[i][j] = 0ull;

    float4 pa0, pa1, pw0, pw1;

    {
        const float* ap = A + (size_t)(m0 + a_m) * ASTRIDE + a_k;
        pa0 = *(const float4*)(ap);
        pa1 = *(const float4*)(ap + 4);
        int gk = w_k;
        if (KSIZE != INREAL) gk = (gk < INREAL) ? gk : (INREAL - 1);
        const float* wp = Wbase + (size_t)gk * OUTN + n0 + w_n;
        pw0 = *(const float4*)(wp);
        pw1 = *(const float4*)(wp + 4);
    }
    {
        ((float2*)(&As2[0][a_k + 0][2 * a_m]))[0] = make_float2(pa0.x, pa0.x);
        ((float2*)(&As2[0][a_k + 1][2 * a_m]))[0] = make_float2(pa0.y, pa0.y);
        ((float2*)(&As2[0][a_k + 2][2 * a_m]))[0] = make_float2(pa0.z, pa0.z);
        ((float2*)(&As2[0][a_k + 3][2 * a_m]))[0] = make_float2(pa0.w, pa0.w);
        ((float2*)(&As2[0][a_k + 4][2 * a_m]))[0] = make_float2(pa1.x, pa1.x);
        ((float2*)(&As2[0][a_k + 5][2 * a_m]))[0] = make_float2(pa1.y, pa1.y);
        ((float2*)(&As2[0][a_k + 6][2 * a_m]))[0] = make_float2(pa1.z, pa1.z);
        ((float2*)(&As2[0][a_k + 7][2 * a_m]))[0] = make_float2(pa1.w, pa1.w);
        *(float4*)&Ws[0][w_k][w_n]     = pw0;
        *(float4*)&Ws[0][w_k][w_n + 4] = pw1;
    }
    __syncthreads();

    for (int kt = 0; kt < KT; kt++) {
        const int buf = kt & 1;
        if (kt + 1 < KT) {
            const int k0 = (kt + 1) * BK;
            const float* ap = A + (size_t)(m0 + a_m) * ASTRIDE + k0 + a_k;
            pa0 = *(const float4*)(ap);
            pa1 = *(const float4*)(ap + 4);
            int gk = k0 + w_k;
            if (KSIZE != INREAL) gk = (gk < INREAL) ? gk : (INREAL - 1);
            const float* wp = Wbase + (size_t)gk * OUTN + n0 + w_n;
            pw0 = *(const float4*)(wp);
            pw1 = *(const float4*)(wp + 4);
        }
#pragma unroll
        for (int k = 0; k < BK; k++) {
            const float* ar = &As2[buf][k][16 * ty];
            ulonglong2 av0 = *(const ulonglong2*)(ar + 0);
            ulonglong2 av1 = *(const ulonglong2*)(ar + 4);
            ulonglong2 av2 = *(const ulonglong2*)(ar + 8);
            ulonglong2 av3 = *(const ulonglong2*)(ar + 12);
            u64 wp_[4];
#pragma unroll
            for (int j = 0; j < 4; j++)
                wp_[j] = *(const u64*)&Ws[buf][k][2 * tx + 32 * j];
            u64 ap_[8] = {av0.x, av0.y, av1.x, av1.y, av2.x, av2.y, av3.x, av3.y};
#pragma unroll
            for (int i = 0; i < 8; i++)
#pragma unroll
                for (int j = 0; j < 4; j++)
                    acc[i][j] = ffma2(ap_[i], wp_[j], acc[i][j]);
        }
        if (kt + 1 < KT) {
            const int nb = buf ^ 1;
            ((float2*)(&As2[nb][a_k + 0][2 * a_m]))[0] = make_float2(pa0.x, pa0.x);
            ((float2*)(&As2[nb][a_k + 1][2 * a_m]))[0] = make_float2(pa0.y, pa0.y);
            ((float2*)(&As2[nb][a_k + 2][2 * a_m]))[0] = make_float2(pa0.z, pa0.z);
            ((float2*)(&As2[nb][a_k + 3][2 * a_m]))[0] = make_float2(pa0.w, pa0.w);
            ((float2*)(&As2[nb][a_k + 4][2 * a_m]))[0] = make_float2(pa1.x, pa1.x);
            ((float2*)(&As2[nb][a_k + 5][2 * a_m]))[0] = make_float2(pa1.y, pa1.y);
            ((float2*)(&As2[nb][a_k + 6][2 * a_m]))[0] = make_float2(pa1.z, pa1.z);
            ((float2*)(&As2[nb][a_k + 7][2 * a_m]))[0] = make_float2(pa1.w, pa1.w);
            *(float4*)&Ws[nb][w_k][w_n]     = pw0;
            *(float4*)&Ws[nb][w_k][w_n + 4] = pw1;
            __syncthreads();
        }
    }

#pragma unroll
    for (int i = 0; i < 8; i++) {
        const int row = m0 + ty * 8 + i;
        float* pb = part + ((size_t)e * BATCH + row) * OUTN + n0;
#pragma unroll
        for (int j = 0; j < 4; j++) {
            const int n = 2 * tx + 32 * j;
            u64 sb = *(const u64*)&sbias[n];
            *(u64*)(pb + n) = fadd2(acc[i][j], sb);
        }
    }
}

// ---------------- gen layer 3: scalar double-buffered (BM=64, TM=4, BN=64) ----------------
template <int KSIZE, int ASTRIDE, int OUTN, int INREAL, int BM, int TM>
__global__ __launch_bounds__(256)
void gen_expert_kernel(const float* __restrict__ A,
                       const float* __restrict__ W,
                       const float* __restrict__ bias,
                       float* __restrict__ part) {
    constexpr int BN = 64, BK = 32;
    constexpr int KT = KSIZE / BK;
    constexpr int F4A = BM * BK / 1024;
    __shared__ __align__(16) float As[2][BK][BM + 4];
    __shared__ __align__(16) float Ws[2][BK][BN];
    __shared__ float sbias[BN];

    const int e  = blockIdx.z;
    const int m0 = blockIdx.y * BM;
    const int n0 = blockIdx.x * BN;
    const int tid = threadIdx.x;
    const int tx = tid & 15;
    const int ty = tid >> 4;

    int a_r[F4A], a_kq[F4A];
#pragma unroll
    for (int j = 0; j < F4A; j++) {
        int idx = tid * F4A + j;
        a_r[j] = idx >> 3;
        a_kq[j] = (idx & 7) * 4;
    }
    const int wk = tid >> 3;
    const int wc = (tid & 7) * 8;

    const float* Wbase = W + (size_t)e * INREAL * OUTN;
    if (tid < BN) sbias[tid] = bias[(size_t)e * OUTN + n0 + tid];

    float acc[TM][4];
#pragma unroll
    for (int i = 0; i < TM; i++)
#pragma unroll
        for (int j = 0; j < 4; j++) acc[i][j] = 0.f;

    float4 pa[F4A];
    float4 pw0, pw1;

    {
#pragma unroll
        for (int j = 0; j < F4A; j++)
            pa[j] = *(const float4*)(A + (size_t)(m0 + a_r[j]) * ASTRIDE + a_kq[j]);
        const float* wp = Wbase + (size_t)wk * OUTN + n0;
        pw0 = *(const float4*)(wp + wc);
        pw1 = *(const float4*)(wp + wc + 4);
    }
    {
#pragma unroll
        for (int j = 0; j < F4A; j++) {
            As[0][a_kq[j] + 0][a_r[j]] = pa[j].x;
            As[0][a_kq[j] + 1][a_r[j]] = pa[j].y;
            As[0][a_kq[j] + 2][a_r[j]] = pa[j].z;
            As[0][a_kq[j] + 3][a_r[j]] = pa[j].w;
        }
        *(float4*)&Ws[0][wk][wc]     = pw0;
        *(float4*)&Ws[0][wk][wc + 4] = pw1;
    }
    __syncthreads();

    for (int kt = 0; kt < KT; kt++) {
        const int buf = kt & 1;
        if (kt + 1 < KT) {
            const int k0 = (kt + 1) * BK;
#pragma unroll
            for (int j = 0; j < F4A; j++)
                pa[j] = *(const float4*)(A + (size_t)(m0 + a_r[j]) * ASTRIDE + k0 + a_kq[j]);
            const float* wp = Wbase + (size_t)(k0 + wk) * OUTN + n0;
            pw0 = *(const float4*)(wp + wc);
            pw1 = *(const float4*)(wp + wc + 4);
        }
#pragma unroll 8
        for (int k = 0; k < BK; k++) {
            float4 w = *(const float4*)&Ws[buf][k][tx * 4];
#pragma unroll
            for (int i4 = 0; i4 < TM / 4; i4++) {
                float4 a = *(const float4*)&As[buf][k][ty * TM + i4 * 4];
                acc[i4 * 4 + 0][0] = fmaf(a.x, w.x, acc[i4 * 4 + 0][0]);
                acc[i4 * 4 + 0][1] = fmaf(a.x, w.y, acc[i4 * 4 + 0][1]);
                acc[i4 * 4 + 0][2] = fmaf(a.x, w.z, acc[i4 * 4 + 0][2]);
                acc[i4 * 4 + 0][3] = fmaf(a.x, w.w, acc[i4 * 4 + 0][3]);
                acc[i4 * 4 + 1][0] = fmaf(a.y, w.x, acc[i4 * 4 + 1][0]);
                acc[i4 * 4 + 1][1] = fmaf(a.y, w.y, acc[i4 * 4 + 1][1]);
                acc[i4 * 4 + 1][2] = fmaf(a.y, w.z, acc[i4 * 4 + 1][2]);
                acc[i4 * 4 + 1][3] = fmaf(a.y, w.w, acc[i4 * 4 + 1][3]);
                acc[i4 * 4 + 2][0] = fmaf(a.z, w.x, acc[i4 * 4 + 2][0]);
                acc[i4 * 4 + 2][1] = fmaf(a.z, w.y, acc[i4 * 4 + 2][1]);
                acc[i4 * 4 + 2][2] = fmaf(a.z, w.z, acc[i4 * 4 + 2][2]);
                acc[i4 * 4 + 2][3] = fmaf(a.z, w.w, acc[i4 * 4 + 2][3]);
                acc[i4 * 4 + 3][0] = fmaf(a.w, w.x, acc[i4 * 4 + 3][0]);
                acc[i4 * 4 + 3][1] = fmaf(a.w, w.y, acc[i4 * 4 + 3][1]);
                acc[i4 * 4 + 3][2] = fmaf(a.w, w.z, acc[i4 * 4 + 3][2]);
                acc[i4 * 4 + 3][3] = fmaf(a.w, w.w, acc[i4 * 4 + 3][3]);
            }
        }
        if (kt + 1 < KT) {
            const int nb = buf ^ 1;
#pragma unroll
            for (int j = 0; j < F4A; j++) {
                As[nb][a_kq[j] + 0][a_r[j]] = pa[j].x;
                As[nb][a_kq[j] + 1][a_r[j]] = pa[j].y;
                As[nb][a_kq[j] + 2][a_r[j]] = pa[j].z;
                As[nb][a_kq[j] + 3][a_r[j]] = pa[j].w;
            }
            *(float4*)&Ws[nb][wk][wc]     = pw0;
            *(float4*)&Ws[nb][wk][wc + 4] = pw1;
            __syncthreads();
        }
    }

#pragma unroll
    for (int i = 0; i < TM; i++) {
        const int row = m0 + ty * TM + i;
        float* pp = part + ((size_t)e * BATCH + row) * OUTN + n0 + tx * 4;
        float4 o;
        o.x = acc[i][0] + sbias[tx * 4 + 0];
        o.y = acc[i][1] + sbias[tx * 4 + 1];
        o.z = acc[i][2] + sbias[tx * 4 + 2];
        o.w = acc[i][3] + sbias[tx * 4 + 3];
        *(float4*)pp = o;
    }
}

// ---------------- combine experts with bc weights (+ optional ELU), vectorized ----------------
template <bool ACT>
__global__ void combine_vec_kernel(const float* __restrict__ part, float* __restrict__ out) {
    const int i = blockIdx.x * 256 + threadIdx.x;
    if (i >= BATCH * (HID / 4)) return;
    const int b = i >> 6;
    const float* bcp = g_bc + (size_t)b * NE;
    float4 s = make_float4(0.f, 0.f, 0.f, 0.f);
#pragma unroll
    for (int e = 0; e < NE; e++) {
        float c = bcp[e];
        float4 p = ((const float4*)part)[(size_t)e * BATCH * (HID / 4) + i];
        s.x = fmaf(c, p.x, s.x);
        s.y = fmaf(c, p.y, s.y);
        s.z = fmaf(c, p.z, s.z);
        s.w = fmaf(c, p.w, s.w);
    }
    if (ACT) {
        s.x = elu1(s.x);
        s.y = elu1(s.y);
        s.z = elu1(s.z);
        s.w = elu1(s.w);
    }
    ((float4*)out)[i] = s;
}

// final combine: padded stride 64 -> write 51
__global__ void combine_final_kernel(const float* __restrict__ part, float* __restrict__ out) {
    const int i = blockIdx.x * 256 + threadIdx.x;
    if (i >= BATCH * DOUT) return;
    const int b = i / DOUT;
    const int n = i - b * DOUT;
    const float* bcp = g_bc + (size_t)b * NE;
    float s = 0.f;
#pragma unroll
    for (int e = 0; e < NE; e++)
        s = fmaf(bcp[e], part[((size_t)e * BATCH + b) * DOPAD + n], s);
    out[i] = s;
}

// ---------------- launch ----------------
extern "C" void kernel_launch(void* const* d_in, const int* in_sizes, int n_in,
                              void* d_out, int out_size) {
    const float* x      = (const float*)d_in[0];
    const float* w1     = (const float*)d_in[1];
    const float* b1     = (const float*)d_in[2];
    const float* gamma1 = (const float*)d_in[3];
    const float* beta1  = (const float*)d_in[4];
    const float* w2     = (const float*)d_in[5];
    const float* b2     = (const float*)d_in[6];
    const float* gamma2 = (const float*)d_in[7];
    const float* beta2  = (const float*)d_in[8];
    const float* gw1    = (const float*)d_in[9];
    const float* gb1    = (const float*)d_in[10];
    const float* gw2    = (const float*)d_in[11];
    const float* gb2    = (const float*)d_in[12];
    const float* gw3    = (const float*)d_in[13];
    const float* gb3    = (const float*)d_in[14];
    const float* ew1    = (const float*)d_in[15];
    const float* eb1    = (const float*)d_in[16];
    const float* ew2    = (const float*)d_in[17];
    const float* eb2    = (const float*)d_in[18];
    const float* ew3    = (const float*)d_in[19];
    const float* eb3    = (const float*)d_in[20];

    float *p_xs, *p_enc1, *p_lat, *p_h1, *p_h2, *p_part, *p_w3p, *p_b3p;
    cudaGetSymbolAddress((void**)&p_xs,   g_xs);
    cudaGetSymbolAddress((void**)&p_enc1, g_enc1);
    cudaGetSymbolAddress((void**)&p_lat,  g_lat);
    cudaGetSymbolAddress((void**)&p_h1,   g_h1);
    cudaGetSymbolAddress((void**)&p_h2,   g_h2);
    cudaGetSymbolAddress((void**)&p_part, g_part);
    cudaGetSymbolAddress((void**)&p_w3p,  g_w3p);
    cudaGetSymbolAddress((void**)&p_b3p,  g_b3p);

    // enc1 (raw-x, pre-scaled weights) + prep fused: blocks 0..63 encoder, 64..191 prep
    enc1_prep_kernel<<<L1W + 128, 256>>>(x, w1, b1, gamma1, beta1, p_enc1, ew3, eb3);

    enc_bn_relu_kernel<16, L1W, L1W, L2W><<<L2W, 256>>>(p_enc1, w2, b2, gamma2, beta2, p_lat);

    // layer 1 + gating fused: z 0..7 = expert GEMMs, z 8..15 = 128 gating blocks
    gen_f32x2_kernel<XPAD, XPAD, HID, DIN, true>
        <<<dim3(HID / 128, BATCH / 128, 2 * NE), 256>>>(
            p_xs, ew1, eb1, p_part,
            p_lat, gw1, gb1, gw2, gb2, gw3, gb3);
    combine_vec_kernel<true><<<(BATCH * HID / 4 + 255) / 256, 256>>>(p_part, p_h1);

    // layer 2: h1[1024,256] x ew2[8,256,256]
    gen_f32x2_kernel<HID, HID, HID, HID, false>
        <<<dim3(HID / 128, BATCH / 128, NE), 256>>>(
            p_h1, ew2, eb2, p_part,
            nullptr, nullptr, nullptr, nullptr, nullptr, nullptr, nullptr);
    combine_vec_kernel<true><<<(BATCH * HID / 4 + 255) / 256, 256>>>(p_part, p_h2);

    // layer 3: h2[1024,256] x w3p[8,256,64(pad)]
    gen_expert_kernel<HID, HID, DOPAD, HID, 64, 4>
        <<<dim3(1, BATCH / 64, NE), 256>>>(p_h2, p_w3p, p_b3p, p_part);
    combine_final_kernel<<<(BATCH * DOUT + 255) / 256, 256>>>(p_part, (float*)d_out);
}